// round 10
// baseline (speedup 1.0000x reference)
#include <cuda_runtime.h>
#include <math.h>

#define BB 128
#define TT 1024
#define DD 512
#define HH 512

// ---------------- scratch ----------------
__device__ float g_xp[(size_t)TT * BB * HH];   // [t][b][h]
__device__ float g_h[2][BB * HH];              // ping-pong hidden state
__device__ unsigned g_ctr[8 * 32];
__device__ unsigned g_gen[8 * 32];

// ---------------- f32x2 helpers ----------------
__device__ __forceinline__ unsigned long long ffma2(unsigned long long a,
                                                    unsigned long long b,
                                                    unsigned long long c) {
    unsigned long long d;
    asm("fma.rn.f32x2 %0, %1, %2, %3;" : "=l"(d) : "l"(a), "l"(b), "l"(c));
    return d;
}
__device__ __forceinline__ unsigned long long pack2(float x, float y) {
    unsigned long long d;
    asm("mov.b64 %0, {%1, %2};" : "=l"(d) : "f"(x), "f"(y));
    return d;
}
__device__ __forceinline__ void unpack2(unsigned long long v, float& x, float& y) {
    asm("mov.b64 {%0, %1}, %2;" : "=f"(x), "=f"(y) : "l"(v));
}

// =====================================================================
// Phase 1: xp = x @ W_ih + b   (unchanged)
// =====================================================================
__global__ void __launch_bounds__(256) xp_gemm_kernel(
        const float* __restrict__ x, const float* __restrict__ Wih,
        const float* __restrict__ bias) {
    __shared__ float As[16][128];
    __shared__ float Bs[16][128];

    const int tid = threadIdx.x;
    const int tx = tid & 15;
    const int ty = tid >> 4;
    const int m0 = blockIdx.y * 128;
    const int n0 = blockIdx.x * 128;

    unsigned long long acc[8][4];
#pragma unroll
    for (int i = 0; i < 8; i++)
#pragma unroll
        for (int j = 0; j < 4; j++) acc[i][j] = 0ull;

    for (int k0 = 0; k0 < DD; k0 += 16) {
#pragma unroll
        for (int q = 0; q < 2; q++) {
            int i = tid + q * 256;
            int row = i >> 2;
            int kc = (i & 3) * 4;
            float4 av = *(const float4*)&x[(size_t)(m0 + row) * DD + k0 + kc];
            As[kc + 0][row] = av.x;
            As[kc + 1][row] = av.y;
            As[kc + 2][row] = av.z;
            As[kc + 3][row] = av.w;
        }
#pragma unroll
        for (int q = 0; q < 2; q++) {
            int i = tid + q * 256;
            int kr = i >> 5;
            int nc = (i & 31) * 4;
            float4 bv = *(const float4*)&Wih[(size_t)(k0 + kr) * HH + n0 + nc];
            *(float4*)&Bs[kr][nc] = bv;
        }
        __syncthreads();

#pragma unroll
        for (int kk = 0; kk < 16; kk++) {
            float4 a0 = *(const float4*)&As[kk][ty * 8];
            float4 a1 = *(const float4*)&As[kk][ty * 8 + 4];
            const unsigned long long* bp =
                (const unsigned long long*)&Bs[kk][tx * 8];
            unsigned long long b0 = bp[0], b1 = bp[1], b2 = bp[2], b3 = bp[3];
            float a[8] = {a0.x, a0.y, a0.z, a0.w, a1.x, a1.y, a1.z, a1.w};
#pragma unroll
            for (int i = 0; i < 8; i++) {
                unsigned long long ap = pack2(a[i], a[i]);
                acc[i][0] = ffma2(ap, b0, acc[i][0]);
                acc[i][1] = ffma2(ap, b1, acc[i][1]);
                acc[i][2] = ffma2(ap, b2, acc[i][2]);
                acc[i][3] = ffma2(ap, b3, acc[i][3]);
            }
        }
        __syncthreads();
    }

    float4 bv0 = *(const float4*)&bias[n0 + tx * 8];
    float4 bv1 = *(const float4*)&bias[n0 + tx * 8 + 4];
    float bb8[8] = {bv0.x, bv0.y, bv0.z, bv0.w, bv1.x, bv1.y, bv1.z, bv1.w};
#pragma unroll
    for (int i = 0; i < 8; i++) {
        int mrow = m0 + ty * 8 + i;
        int b_ = mrow >> 10;
        int t_ = mrow & 1023;
        float f[8];
        unpack2(acc[i][0], f[0], f[1]);
        unpack2(acc[i][1], f[2], f[3]);
        unpack2(acc[i][2], f[4], f[5]);
        unpack2(acc[i][3], f[6], f[7]);
#pragma unroll
        for (int j = 0; j < 8; j++) f[j] += bb8[j];
        float* dst = &g_xp[((size_t)t_ * BB + b_) * HH + n0 + tx * 8];
        *(float4*)&dst[0] = make_float4(f[0], f[1], f[2], f[3]);
        *(float4*)&dst[4] = make_float4(f[4], f[5], f[6], f[7]);
    }
}

// =====================================================================
// Phase 2 v6: broadcast-LDS layout, 512 threads.
//   warp w (0..15) owns k-range w*32..+31 (k split across WARPS)
//   lane = column (col0+lane)  -> every h LDS is a 32-lane broadcast
//   thread: 16 rows x 1 col x 32 k; W = 16 ull, acc = 16 ull (~85 regs)
// k-reduction across warps via smem partial buffer (16 adds/output).
// =====================================================================
__global__ void __launch_bounds__(512) rnn_steps_kernel(
        const float* __restrict__ Whh, float* __restrict__ out) {
    extern __shared__ float smemf[];
    float4* hs4 = (float4*)smemf;            // [16*128] float4 = 32 KB (linear)
    float*  pb  = smemf + 2048 * 4;          // [16 warps][16 rows][32 cols] = 32 KB

    const int tid = threadIdx.x;
    const int warp = tid >> 5, lane = tid & 31;

    const int mg = blockIdx.x >> 4;     // 0..7
    const int ng = blockIdx.x & 15;     // 0..15
    const int row0 = mg * 16;
    const int col0 = ng * 32;

    const int col = col0 + lane;        // this thread's W/h column
    const int k0w = warp * 32;          // this warp's k-range

    // ---- one-time W load: wr[kk] = (W[k0w+2kk][col], W[k0w+2kk+1][col])
    unsigned long long wr[16];
#pragma unroll
    for (int kk = 0; kk < 16; kk++) {
        const float* p = Whh + (size_t)(k0w + 2 * kk) * HH + col;
        wr[kk] = pack2(p[0], p[HH]);
    }

    // output ownership: thread (r2 = warp, c2 = lane)
    const int r2 = warp;
    const int c2 = lane;
    const int orow = row0 + r2;
    const int ocol = col0 + c2;

    unsigned* ctr = &g_ctr[mg * 32];
    volatile unsigned* gen = &g_gen[mg * 32];

    // ---------------- t = 0 (h = 0) ----------------
    {
        float xv = g_xp[(size_t)orow * HH + ocol];
        float hv = tanhf(xv);
        g_h[1][(size_t)orow * HH + ocol] = hv;
        __threadfence();
        __syncthreads();
        if (tid == 0) {
            unsigned g = *gen;
            unsigned tk = atomicAdd(ctr, 1u);
            if (tk == 15u) {
                *(volatile unsigned*)ctr = 0u;
                __threadfence();
                atomicAdd((unsigned*)gen, 1u);
            } else {
                while (*gen == g) { }
            }
            __threadfence();
        }
        __syncthreads();
    }

    // ---------------- t = 1 .. TT-1 ----------------
    for (int t = 1; t < TT; t++) {
        // prefetch xp for this thread's output
        float xv = __ldcg(&g_xp[((size_t)t * BB + orow) * HH + ocol]);

        // cooperative linear load of the 16 h rows (32 KB)
        const float4* hin4 = (const float4*)g_h[t & 1] + (size_t)row0 * 128;
#pragma unroll
        for (int q = 0; q < 4; q++) {
            int idx = tid + q * 512;
            hs4[idx] = __ldcg(hin4 + idx);
        }
        __syncthreads();

        // ---- compute: acc[r] = sum over this warp's 32 k (as k-pairs)
        unsigned long long acc[16];
#pragma unroll
        for (int r = 0; r < 16; r++) acc[r] = 0ull;

        const ulonglong2* hbase = (const ulonglong2*)hs4 + warp * 8;
#pragma unroll
        for (int r = 0; r < 16; r++) {
            const ulonglong2* hp = hbase + r * 128;   // row stride = 128 (16B units)
#pragma unroll
            for (int j = 0; j < 8; j++) {
                ulonglong2 hv2 = hp[j];               // broadcast: all lanes same addr
                acc[r] = ffma2(hv2.x, wr[2 * j], acc[r]);
                acc[r] = ffma2(hv2.y, wr[2 * j + 1], acc[r]);
            }
        }

        // ---- fold k-pairs, store partials: pb[warp][r][lane]
#pragma unroll
        for (int r = 0; r < 16; r++) {
            float a, b;
            unpack2(acc[r], a, b);
            pb[(warp * 16 + r) * 32 + lane] = a + b;
        }
        __syncthreads();

        // ---- owner reduce over 16 warps' partials
        float s = 0.0f;
#pragma unroll
        for (int w2 = 0; w2 < 16; w2++) s += pb[(w2 * 16 + r2) * 32 + c2];

        float hv = tanhf(xv + s);
        g_h[(t + 1) & 1][(size_t)orow * HH + ocol] = hv;
        if (t == TT - 1) out[(size_t)orow * HH + ocol] = hv;

        // ---- m-group barrier (16 CTAs) ----
        __threadfence();
        __syncthreads();
        if (tid == 0) {
            unsigned g = *gen;
            unsigned tk = atomicAdd(ctr, 1u);
            if (tk == 15u) {
                *(volatile unsigned*)ctr = 0u;
                __threadfence();
                atomicAdd((unsigned*)gen, 1u);
            } else {
                while (*gen == g) { }
            }
            __threadfence();
        }
        __syncthreads();
    }
}

// =====================================================================
extern "C" void kernel_launch(void* const* d_in, const int* in_sizes, int n_in,
                              void* d_out, int out_size) {
    const float* x    = (const float*)d_in[0];
    const float* Wih  = (const float*)d_in[1];
    const float* Whh  = (const float*)d_in[2];
    const float* bias = (const float*)d_in[3];
    float* out = (float*)d_out;

    const int smem2 = 2048 * 16 + 8192 * 4;   // 32KB h + 32KB partials = 64 KB
    cudaFuncSetAttribute(rnn_steps_kernel,
                         cudaFuncAttributeMaxDynamicSharedMemorySize, smem2);

    dim3 g1(HH / 128, (BB * TT) / 128);   // (4, 1024)
    xp_gemm_kernel<<<g1, 256>>>(x, Wih, bias);
    rnn_steps_kernel<<<128, 512, smem2>>>(Whh, out);
}

// round 13
// speedup vs baseline: 1.0608x; 1.0608x over previous
#include <cuda_runtime.h>
#include <math.h>

#define BB 128
#define TT 1024
#define DD 512
#define HH 512

// ---------------- scratch ----------------
__device__ float g_xp[(size_t)TT * BB * HH];   // [t][b][h]
__device__ float g_h[2][BB * HH];              // ping-pong hidden state
__device__ unsigned g_ctr[8 * 32];             // per m-group arrival counter
__device__ unsigned g_gen[8 * 32];             // per m-group generation

// ---------------- f32x2 helpers ----------------
__device__ __forceinline__ unsigned long long ffma2(unsigned long long a,
                                                    unsigned long long b,
                                                    unsigned long long c) {
    unsigned long long d;
    asm("fma.rn.f32x2 %0, %1, %2, %3;" : "=l"(d) : "l"(a), "l"(b), "l"(c));
    return d;
}
__device__ __forceinline__ unsigned long long pack2(float x, float y) {
    unsigned long long d;
    asm("mov.b64 %0, {%1, %2};" : "=l"(d) : "f"(x), "f"(y));
    return d;
}
__device__ __forceinline__ void unpack2(unsigned long long v, float& x, float& y) {
    asm("mov.b64 {%0, %1}, %2;" : "=f"(x), "=f"(y) : "l"(v));
}

// ---------------- scoped atomics (no per-thread fences) ----------------
__device__ __forceinline__ unsigned atom_add_acqrel(unsigned* p, unsigned v) {
    unsigned old;
    asm volatile("atom.acq_rel.gpu.global.add.u32 %0, [%1], %2;"
                 : "=r"(old) : "l"(p), "r"(v) : "memory");
    return old;
}
__device__ __forceinline__ unsigned ld_acquire(unsigned* p) {
    unsigned v;
    asm volatile("ld.acquire.gpu.global.u32 %0, [%1];"
                 : "=r"(v) : "l"(p) : "memory");
    return v;
}
__device__ __forceinline__ void st_relaxed(unsigned* p, unsigned v) {
    asm volatile("st.relaxed.gpu.global.u32 [%0], %1;"
                 :: "l"(p), "r"(v) : "memory");
}

// group barrier: all threads call; tid0 arrives/polls; bar.sync broadcasts.
__device__ __forceinline__ void group_barrier(int tid, unsigned* ctr, unsigned* gen) {
    __syncthreads();                       // all producers' stores issued
    if (tid == 0) {
        unsigned g = ld_acquire(gen);      // generation before arrival
        unsigned tk = atom_add_acqrel(ctr, 1u);
        if (tk == 15u) {
            st_relaxed(ctr, 0u);           // published by the release below
            atom_add_acqrel(gen, 1u);      // release: h stores + ctr reset
        } else {
            while (ld_acquire(gen) == g) { __nanosleep(64); }
        }
    }
    __syncthreads();                       // broadcast release to whole CTA
}

// =====================================================================
// Phase 1: xp = x @ W_ih + b   (unchanged)
// =====================================================================
__global__ void __launch_bounds__(256) xp_gemm_kernel(
        const float* __restrict__ x, const float* __restrict__ Wih,
        const float* __restrict__ bias) {
    __shared__ float As[16][128];
    __shared__ float Bs[16][128];

    const int tid = threadIdx.x;
    const int tx = tid & 15;
    const int ty = tid >> 4;
    const int m0 = blockIdx.y * 128;
    const int n0 = blockIdx.x * 128;

    unsigned long long acc[8][4];
#pragma unroll
    for (int i = 0; i < 8; i++)
#pragma unroll
        for (int j = 0; j < 4; j++) acc[i][j] = 0ull;

    for (int k0 = 0; k0 < DD; k0 += 16) {
#pragma unroll
        for (int q = 0; q < 2; q++) {
            int i = tid + q * 256;
            int row = i >> 2;
            int kc = (i & 3) * 4;
            float4 av = *(const float4*)&x[(size_t)(m0 + row) * DD + k0 + kc];
            As[kc + 0][row] = av.x;
            As[kc + 1][row] = av.y;
            As[kc + 2][row] = av.z;
            As[kc + 3][row] = av.w;
        }
#pragma unroll
        for (int q = 0; q < 2; q++) {
            int i = tid + q * 256;
            int kr = i >> 5;
            int nc = (i & 31) * 4;
            float4 bv = *(const float4*)&Wih[(size_t)(k0 + kr) * HH + n0 + nc];
            *(float4*)&Bs[kr][nc] = bv;
        }
        __syncthreads();

#pragma unroll
        for (int kk = 0; kk < 16; kk++) {
            float4 a0 = *(const float4*)&As[kk][ty * 8];
            float4 a1 = *(const float4*)&As[kk][ty * 8 + 4];
            const unsigned long long* bp =
                (const unsigned long long*)&Bs[kk][tx * 8];
            unsigned long long b0 = bp[0], b1 = bp[1], b2 = bp[2], b3 = bp[3];
            float a[8] = {a0.x, a0.y, a0.z, a0.w, a1.x, a1.y, a1.z, a1.w};
#pragma unroll
            for (int i = 0; i < 8; i++) {
                unsigned long long ap = pack2(a[i], a[i]);
                acc[i][0] = ffma2(ap, b0, acc[i][0]);
                acc[i][1] = ffma2(ap, b1, acc[i][1]);
                acc[i][2] = ffma2(ap, b2, acc[i][2]);
                acc[i][3] = ffma2(ap, b3, acc[i][3]);
            }
        }
        __syncthreads();
    }

    float4 bv0 = *(const float4*)&bias[n0 + tx * 8];
    float4 bv1 = *(const float4*)&bias[n0 + tx * 8 + 4];
    float bb8[8] = {bv0.x, bv0.y, bv0.z, bv0.w, bv1.x, bv1.y, bv1.z, bv1.w};
#pragma unroll
    for (int i = 0; i < 8; i++) {
        int mrow = m0 + ty * 8 + i;
        int b_ = mrow >> 10;
        int t_ = mrow & 1023;
        float f[8];
        unpack2(acc[i][0], f[0], f[1]);
        unpack2(acc[i][1], f[2], f[3]);
        unpack2(acc[i][2], f[4], f[5]);
        unpack2(acc[i][3], f[6], f[7]);
#pragma unroll
        for (int j = 0; j < 8; j++) f[j] += bb8[j];
        float* dst = &g_xp[((size_t)t_ * BB + b_) * HH + n0 + tx * 8];
        *(float4*)&dst[0] = make_float4(f[0], f[1], f[2], f[3]);
        *(float4*)&dst[4] = make_float4(f[4], f[5], f[6], f[7]);
    }
}

// =====================================================================
// Phase 2 v7: broadcast-LDS compute + acq/rel group barrier + xp pipeline
// =====================================================================
__global__ void __launch_bounds__(512) rnn_steps_kernel(
        const float* __restrict__ Whh, float* __restrict__ out) {
    extern __shared__ float smemf[];
    float4* hs4 = (float4*)smemf;            // [16*128] float4 = 32 KB
    float*  pb  = smemf + 2048 * 4;          // [16 warps][16 rows][32 cols] = 32 KB

    const int tid = threadIdx.x;
    const int warp = tid >> 5, lane = tid & 31;

    const int mg = blockIdx.x >> 4;
    const int ng = blockIdx.x & 15;
    const int row0 = mg * 16;
    const int col0 = ng * 32;

    const int col = col0 + lane;
    const int k0w = warp * 32;

    // ---- one-time W load: wr[kk] = (W[k0w+2kk][col], W[k0w+2kk+1][col])
    unsigned long long wr[16];
#pragma unroll
    for (int kk = 0; kk < 16; kk++) {
        const float* p = Whh + (size_t)(k0w + 2 * kk) * HH + col;
        wr[kk] = pack2(p[0], p[HH]);
    }

    const int orow = row0 + warp;
    const int ocol = col0 + lane;

    unsigned* ctr = &g_ctr[mg * 32];
    unsigned* gen = &g_gen[mg * 32];

    // ---------------- t = 0 (h = 0) ----------------
    {
        float xv = __ldcg(&g_xp[(size_t)orow * HH + ocol]);
        float hv = tanhf(xv);
        g_h[1][(size_t)orow * HH + ocol] = hv;
        group_barrier(tid, ctr, gen);
    }

    float xv = __ldcg(&g_xp[((size_t)1 * BB + orow) * HH + ocol]);

    // ---------------- t = 1 .. TT-1 ----------------
    for (int t = 1; t < TT; t++) {
        // cooperative linear load of the 16 h rows (32 KB via L2)
        const float4* hin4 = (const float4*)g_h[t & 1] + (size_t)row0 * 128;
#pragma unroll
        for (int q = 0; q < 4; q++) {
            int idx = tid + q * 512;
            hs4[idx] = __ldcg(hin4 + idx);
        }
        // prefetch next step's xp while compute runs
        float xv_next = 0.0f;
        if (t + 1 < TT)
            xv_next = __ldcg(&g_xp[((size_t)(t + 1) * BB + orow) * HH + ocol]);
        __syncthreads();

        // ---- compute: acc[r] = partial dot over this warp's 32 k
        unsigned long long acc[16];
#pragma unroll
        for (int r = 0; r < 16; r++) acc[r] = 0ull;

        const ulonglong2* hbase = (const ulonglong2*)hs4 + warp * 8;
#pragma unroll
        for (int r = 0; r < 16; r++) {
            const ulonglong2* hp = hbase + r * 128;
#pragma unroll
            for (int j = 0; j < 8; j++) {
                ulonglong2 hv2 = hp[j];               // 32-lane broadcast
                acc[r] = ffma2(hv2.x, wr[2 * j], acc[r]);
                acc[r] = ffma2(hv2.y, wr[2 * j + 1], acc[r]);
            }
        }

        // ---- fold pairs, store partials pb[warp][r][lane]
#pragma unroll
        for (int r = 0; r < 16; r++) {
            float a, b;
            unpack2(acc[r], a, b);
            pb[(warp * 16 + r) * 32 + lane] = a + b;
        }
        __syncthreads();

        // ---- owner (row = warp, col = lane) reduces 16 warp partials
        float s = 0.0f;
#pragma unroll
        for (int w2 = 0; w2 < 16; w2++) s += pb[(w2 * 16 + warp) * 32 + lane];

        float hv = tanhf(xv + s);
        g_h[(t + 1) & 1][(size_t)orow * HH + ocol] = hv;
        if (t == TT - 1) out[(size_t)orow * HH + ocol] = hv;

        // ---- m-group barrier (release/acquire, tid0 only) ----
        group_barrier(tid, ctr, gen);

        xv = xv_next;
    }
}

// =====================================================================
extern "C" void kernel_launch(void* const* d_in, const int* in_sizes, int n_in,
                              void* d_out, int out_size) {
    const float* x    = (const float*)d_in[0];
    const float* Wih  = (const float*)d_in[1];
    const float* Whh  = (const float*)d_in[2];
    const float* bias = (const float*)d_in[3];
    float* out = (float*)d_out;

    const int smem2 = 2048 * 16 + 8192 * 4;   // 64 KB
    cudaFuncSetAttribute(rnn_steps_kernel,
                         cudaFuncAttributeMaxDynamicSharedMemorySize, smem2);

    dim3 g1(HH / 128, (BB * TT) / 128);   // (4, 1024)
    xp_gemm_kernel<<<g1, 256>>>(x, Wih, bias);
    rnn_steps_kernel<<<128, 512, smem2>>>(Whh, out);
}